// round 2
// baseline (speedup 1.0000x reference)
#include <cuda_runtime.h>
#include <math.h>

#define B_  32768
#define H_  512
#define BM  128
#define BN  64
#define BK  16
#define TM  8
#define TN  4
#define NTHREADS 256

// ---------------- static device scratch (allowed per harness rules) -----------
__device__ int   g_cnt[2];
__device__ int   g_idx0[B_];
__device__ int   g_idx1[B_];
__device__ int   g_pos[B_];
__device__ float g_h1l[(size_t)B_ * H_];   // 1: left  branch layer-1 output (compact)
__device__ float g_h1r[(size_t)B_ * H_];   // 2: right branch layer-1 output (compact)
__device__ float g_outl[(size_t)B_ * H_];  // 3: left  branch layer-2 output (compact)
__device__ float g_outr[(size_t)B_ * H_];  // 4: right branch layer-2 output (compact)

// Device-side resolution of internal scratch buffers (ids 1..4).
__device__ __forceinline__ float* scratch_buf(int id) {
    switch (id) {
        case 1:  return g_h1l;
        case 2:  return g_h1r;
        case 3:  return g_outl;
        default: return g_outr;
    }
}

// ---------------- small helper kernels ---------------------------------------
__global__ void zero_cnt_kernel() {
    if (threadIdx.x < 2) g_cnt[threadIdx.x] = 0;
}

__global__ void build_idx_kernel(const int* __restrict__ group,
                                 float* __restrict__ mask_out, int write_mask) {
    int i = blockIdx.x * blockDim.x + threadIdx.x;
    if (i >= B_) return;
    int g = group[i];
    if (write_mask) mask_out[i] = (g == 2) ? 1.0f : 0.0f;
    if (g == 0) {
        int p = atomicAdd(&g_cnt[0], 1);
        g_idx0[p] = i;
        g_pos[i]  = p;
    } else if (g == 1) {
        int p = atomicAdd(&g_cnt[1], 1);
        g_idx1[p] = i;
        g_pos[i]  = p;
    } else {
        g_pos[i] = -1;
    }
}

// ---------------- fused gated GEMM --------------------------------------------
// out[m, n] = tanh( sum_k A[m,k]*Wh[k,n] + bh[n] ) * sigmoid( sum_k A[m,k]*Wg[k,n] + bg[n] )
// A is nseg concatenated segments, each 512 cols wide, row-major.
// Per segment: if iseg_id[s] > 0 the segment comes from internal scratch
// (compact rows, direct indexing); otherwise from the external pointer, with
// gather through the idx list if (gather_mask >> s) & 1.
__global__ __launch_bounds__(NTHREADS, 2)
void gate_gemm_kernel(const float* __restrict__ eseg0,
                      const float* __restrict__ eseg1,
                      const float* __restrict__ eseg2,
                      int iseg0, int iseg1, int iseg2,
                      int nseg, unsigned gather_mask,
                      int cnt_sel, int idx_sel,
                      const float* __restrict__ Wh, const float* __restrict__ bh,
                      const float* __restrict__ Wg, const float* __restrict__ bg,
                      int out_id)
{
    const int mcnt = g_cnt[cnt_sel];
    const int m0 = blockIdx.y * BM;
    if (m0 >= mcnt) return;
    const int n0 = blockIdx.x * BN;

    __shared__ float As[BK][BM + 4];
    __shared__ float Whs[BK][BN];
    __shared__ float Wgs[BK][BN];
    __shared__ int   rid_g[BM];          // gathered source rows (or -1)
    __shared__ int   rid_d[BM];          // direct   source rows (or -1)

    const int tid = threadIdx.x;
    const int* __restrict__ idx = (idx_sel == 0) ? g_idx0 : g_idx1;

    for (int i = tid; i < BM; i += NTHREADS) {
        int m = m0 + i;
        bool v = (m < mcnt);
        rid_d[i] = v ? m : -1;
        rid_g[i] = v ? idx[m] : -1;
    }
    __syncthreads();

    float acc_h[TM][TN];
    float acc_g[TM][TN];
#pragma unroll
    for (int i = 0; i < TM; ++i)
#pragma unroll
        for (int j = 0; j < TN; ++j) { acc_h[i][j] = 0.f; acc_g[i][j] = 0.f; }

    const float* segs[3];
    segs[0] = (iseg0 > 0) ? scratch_buf(iseg0) : eseg0;
    segs[1] = (iseg1 > 0) ? scratch_buf(iseg1) : eseg1;
    segs[2] = (iseg2 > 0) ? scratch_buf(iseg2) : eseg2;
    const int K = nseg * H_;

    const int ty = tid >> 4;   // 0..15 -> rows ty*8 .. ty*8+7
    const int tx = tid & 15;   // 0..15 -> cols tx*4 .. tx*4+3

    for (int k0 = 0; k0 < K; k0 += BK) {
        const int s  = k0 >> 9;        // segment (512 wide each)
        const int kk = k0 & 511;       // offset inside segment
        const float* __restrict__ A = segs[s];
        const int* __restrict__ rid = ((gather_mask >> s) & 1u) ? rid_g : rid_d;

        // ---- load A tile: 128 rows x 16 k, float4 along k (512 float4 / 256 thr)
#pragma unroll
        for (int it = 0; it < 2; ++it) {
            int li   = tid + it * NTHREADS;  // 0..511
            int lrow = li >> 2;              // 0..127
            int lq   = li & 3;               // k-quad
            int r = rid[lrow];
            float4 v;
            if (r >= 0)
                v = *reinterpret_cast<const float4*>(A + (size_t)r * H_ + kk + lq * 4);
            else
                v = make_float4(0.f, 0.f, 0.f, 0.f);
            As[lq * 4 + 0][lrow] = v.x;
            As[lq * 4 + 1][lrow] = v.y;
            As[lq * 4 + 2][lrow] = v.z;
            As[lq * 4 + 3][lrow] = v.w;
        }
        // ---- load W tiles: 16 x 64 each, one float4 per thread
        {
            int lrow = tid >> 4;             // k row 0..15
            int lc   = (tid & 15) * 4;       // n col
            const float* wp = Wh + (size_t)(k0 + lrow) * H_ + n0 + lc;
            *reinterpret_cast<float4*>(&Whs[lrow][lc]) =
                *reinterpret_cast<const float4*>(wp);
            const float* wq = Wg + (size_t)(k0 + lrow) * H_ + n0 + lc;
            *reinterpret_cast<float4*>(&Wgs[lrow][lc]) =
                *reinterpret_cast<const float4*>(wq);
        }
        __syncthreads();

#pragma unroll
        for (int kki = 0; kki < BK; ++kki) {
            float a[TM], wh[TN], wg[TN];
#pragma unroll
            for (int i = 0; i < TM; ++i) a[i] = As[kki][ty * TM + i];
#pragma unroll
            for (int j = 0; j < TN; ++j) {
                wh[j] = Whs[kki][tx * TN + j];
                wg[j] = Wgs[kki][tx * TN + j];
            }
#pragma unroll
            for (int i = 0; i < TM; ++i)
#pragma unroll
                for (int j = 0; j < TN; ++j) {
                    acc_h[i][j] = fmaf(a[i], wh[j], acc_h[i][j]);
                    acc_g[i][j] = fmaf(a[i], wg[j], acc_g[i][j]);
                }
        }
        __syncthreads();
    }

    // ---- epilogue: bias + tanh*sigmoid, store compact rows
    float* __restrict__ out = scratch_buf(out_id);
#pragma unroll
    for (int j = 0; j < TN; ++j) {
        int n = n0 + tx * TN + j;
        float bhv = bh[n];
        float bgv = bg[n];
#pragma unroll
        for (int i = 0; i < TM; ++i) {
            int m = m0 + ty * TM + i;
            if (m < mcnt) {
                float x = acc_h[i][j] + bhv;
                float y = acc_g[i][j] + bgv;
                float r = tanhf(x) * (1.0f / (1.0f + expf(-y)));
                out[(size_t)m * H_ + n] = r;
            }
        }
    }
}

// ---------------- final select/scatter ----------------------------------------
__global__ void combine_kernel(const int* __restrict__ group,
                               float* __restrict__ out)
{
    int t = blockIdx.x * blockDim.x + threadIdx.x;   // per float4
    const int total = B_ * (H_ / 4);
    if (t >= total) return;
    int row = t / (H_ / 4);
    int c4  = t % (H_ / 4);
    int g = group[row];
    float4 v;
    if (g == 0) {
        v = reinterpret_cast<const float4*>(g_outl + (size_t)g_pos[row] * H_)[c4];
    } else if (g == 1) {
        v = reinterpret_cast<const float4*>(g_outr + (size_t)g_pos[row] * H_)[c4];
    } else {
        v = make_float4(0.f, 0.f, 0.f, 0.f);
    }
    reinterpret_cast<float4*>(out)[t] = v;
}

// ---------------- launch -------------------------------------------------------
extern "C" void kernel_launch(void* const* d_in, const int* in_sizes, int n_in,
                              void* d_out, int out_size)
{
    const float* node_hidden     = (const float*)d_in[0];
    const float* node_context    = (const float*)d_in[1];
    const float* label_embedding = (const float*)d_in[2];
    const float* left_embedding  = (const float*)d_in[3];
    const int*   group           = (const int*)  d_in[4];
    const float* Wl1h = (const float*)d_in[5];
    const float* bl1h = (const float*)d_in[6];
    const float* Wl1g = (const float*)d_in[7];
    const float* bl1g = (const float*)d_in[8];
    const float* Wl2h = (const float*)d_in[9];
    const float* bl2h = (const float*)d_in[10];
    const float* Wl2g = (const float*)d_in[11];
    const float* bl2g = (const float*)d_in[12];
    const float* Wr1h = (const float*)d_in[13];
    const float* br1h = (const float*)d_in[14];
    const float* Wr1g = (const float*)d_in[15];
    const float* br1g = (const float*)d_in[16];
    const float* Wr2h = (const float*)d_in[17];
    const float* br2h = (const float*)d_in[18];
    const float* Wr2g = (const float*)d_in[19];
    const float* br2g = (const float*)d_in[20];
    (void)in_sizes; (void)n_in;

    float* out_children = (float*)d_out;
    float* out_mask     = (float*)d_out + (size_t)B_ * H_;
    int write_mask = (out_size >= (int)((size_t)B_ * H_ + B_)) ? 1 : 0;

    // reset + build gather lists (+ mask)
    zero_cnt_kernel<<<1, 32>>>();
    build_idx_kernel<<<B_ / 256, 256>>>(group, out_mask, write_mask);

    dim3 grid(H_ / BN, (B_ + BM - 1) / BM);   // 8 x 256; inactive M-blocks early-exit

    // left branch, layer 1: x1 = [node_hidden | node_context | label_embedding] (all gathered)
    gate_gemm_kernel<<<grid, NTHREADS>>>(node_hidden, node_context, label_embedding,
                                         0, 0, 0,
                                         3, 0x7u, 0, 0,
                                         Wl1h, bl1h, Wl1g, bl1g, /*out=*/1);
    // right branch, layer 1
    gate_gemm_kernel<<<grid, NTHREADS>>>(node_hidden, node_context, label_embedding,
                                         0, 0, 0,
                                         3, 0x7u, 1, 1,
                                         Wr1h, br1h, Wr1g, br1g, /*out=*/2);
    // left branch, layer 2: x2 = h1l (internal compact, direct rows)
    gate_gemm_kernel<<<grid, NTHREADS>>>(nullptr, nullptr, nullptr,
                                         1, 0, 0,
                                         1, 0x0u, 0, 0,
                                         Wl2h, bl2h, Wl2g, bl2g, /*out=*/3);
    // right branch, layer 2: x2 = [h1r (internal direct) | left_embedding (gathered)]
    gate_gemm_kernel<<<grid, NTHREADS>>>(nullptr, left_embedding, nullptr,
                                         2, 0, 0,
                                         2, 0x2u, 1, 1,
                                         Wr2h, br2h, Wr2g, br2g, /*out=*/4);
    // scatter/select into final output
    combine_kernel<<<(B_ * (H_ / 4) + 255) / 256, 256>>>(group, out_children);
}

// round 4
// speedup vs baseline: 1.9941x; 1.9941x over previous
#include <cuda_runtime.h>
#include <cuda_bf16.h>
#include <cstdint>
#include <math.h>

#define B_ 32768
#define H_ 512
typedef __nv_bfloat16 bf16;

// ---- GEMM tiles ----
#define CTA_M 128
#define BK 32
#define NTH 256
#define ROWB 80                     // 64B data + 16B pad per 128-row plane row
#define PLANE_B (128 * ROWB)        // 10240
#define STAGE_B (4 * PLANE_B)       // 40960 (A_hi, A_lo, B_hi, B_lo)
#define SMEM_DYN (2 * STAGE_B)      // 81920

// ---- static device scratch ----
__device__ int g_cnt[2];
__device__ int g_idx[2][B_];
__device__ __align__(16) bf16 g_x1_hi[2][(size_t)B_ * 1536];
__device__ __align__(16) bf16 g_x1_lo[2][(size_t)B_ * 1536];
__device__ __align__(16) bf16 g_le_hi[(size_t)B_ * 512];
__device__ __align__(16) bf16 g_le_lo[(size_t)B_ * 512];
__device__ __align__(16) bf16 g_h1_hi[2][(size_t)B_ * 512];
__device__ __align__(16) bf16 g_h1_lo[2][(size_t)B_ * 512];
#define WI_TOTAL 4718592            // (1536+1536+512+1024)*1024
__device__ __align__(16) bf16 g_wi_hi[WI_TOTAL];
__device__ __align__(16) bf16 g_wi_lo[WI_TOTAL];

__constant__ int c_jobK[4]  = {1536, 1536, 512, 1024};
__constant__ int c_wioff[4] = {0, 1572864, 3145728, 3670016};

// ---- PTX helpers (all baseline ISA, no 'a'-gated features) ----
__device__ __forceinline__ uint32_t smem_u32(const void* p) {
    uint32_t a;
    asm("{ .reg .u64 t; cvta.to.shared.u64 t, %1; cvt.u32.u64 %0, t; }" : "=r"(a) : "l"(p));
    return a;
}
#define CP_ASYNC16(d, s) asm volatile("cp.async.cg.shared.global [%0], [%1], 16;" :: "r"(d), "l"(s))
#define CP_COMMIT()      asm volatile("cp.async.commit_group;" ::: "memory")
#define CP_WAIT1()       asm volatile("cp.async.wait_group 1;" ::: "memory")
#define CP_WAIT0()       asm volatile("cp.async.wait_group 0;" ::: "memory")
#define LDSM_X4(r, addr) \
    asm volatile("ldmatrix.sync.aligned.m8n8.x4.shared.b16 {%0,%1,%2,%3}, [%4];" \
        : "=r"((r)[0]), "=r"((r)[1]), "=r"((r)[2]), "=r"((r)[3]) : "r"(addr))
#define MMA_BF16(c, a, b) \
    asm volatile("mma.sync.aligned.m16n8k16.row.col.f32.bf16.bf16.f32 " \
        "{%0,%1,%2,%3}, {%4,%5,%6,%7}, {%8,%9}, {%0,%1,%2,%3};" \
        : "+f"((c)[0]), "+f"((c)[1]), "+f"((c)[2]), "+f"((c)[3]) \
        : "r"((a)[0]), "r"((a)[1]), "r"((a)[2]), "r"((a)[3]), "r"((b)[0]), "r"((b)[1]))

// ---- small kernels ----
__global__ void zero_cnt_kernel() { if (threadIdx.x < 2) g_cnt[threadIdx.x] = 0; }

__global__ void build_idx_kernel(const int* __restrict__ group,
                                 float* __restrict__ mask_out, int write_mask) {
    int i = blockIdx.x * blockDim.x + threadIdx.x;
    if (i >= B_) return;
    int g = group[i];
    if (write_mask) mask_out[i] = (g == 2) ? 1.0f : 0.0f;
    if (g == 0)      { int p = atomicAdd(&g_cnt[0], 1); g_idx[0][p] = i; }
    else if (g == 1) { int p = atomicAdd(&g_cnt[1], 1); g_idx[1][p] = i; }
}

__global__ void zero_out_kernel(float* __restrict__ out) {
    int t = blockIdx.x * blockDim.x + threadIdx.x;
    if (t < B_ * (H_ / 4))
        reinterpret_cast<float4*>(out)[t] = make_float4(0.f, 0.f, 0.f, 0.f);
}

// weight prepack: [K,512] Wh,Wg -> interleaved transposed rows [2n+p][K], split bf16 hi/lo
__global__ void prepack_wi_kernel(const float* w0h, const float* w0g,
                                  const float* w1h, const float* w1g,
                                  const float* w2h, const float* w2g,
                                  const float* w3h, const float* w3g) {
    int j = blockIdx.z;
    const float* Wh = (j == 0) ? w0h : (j == 1) ? w1h : (j == 2) ? w2h : w3h;
    const float* Wg = (j == 0) ? w0g : (j == 1) ? w1g : (j == 2) ? w2g : w3g;
    int K = c_jobK[j];
    int k0 = blockIdx.x * 32;
    if (k0 >= K) return;
    int n0 = blockIdx.y * 32;
    __shared__ float sh[32][33], sg[32][33];
    int tx = threadIdx.x, ty = threadIdx.y;
#pragma unroll
    for (int i = 0; i < 4; ++i) {
        sh[ty + 8 * i][tx] = Wh[(size_t)(k0 + ty + 8 * i) * 512 + n0 + tx];
        sg[ty + 8 * i][tx] = Wg[(size_t)(k0 + ty + 8 * i) * 512 + n0 + tx];
    }
    __syncthreads();
    size_t base = (size_t)c_wioff[j];
#pragma unroll
    for (int i = 0; i < 4; ++i) {
        int n = n0 + ty + 8 * i;
        int k = k0 + tx;
        float vh = sh[tx][ty + 8 * i];
        float vg = sg[tx][ty + 8 * i];
        bf16 hh = __float2bfloat16(vh);
        bf16 gh = __float2bfloat16(vg);
        size_t rh = base + (size_t)(2 * n) * K + k;
        size_t rg = base + (size_t)(2 * n + 1) * K + k;
        g_wi_hi[rh] = hh; g_wi_lo[rh] = __float2bfloat16(vh - __bfloat162float(hh));
        g_wi_hi[rg] = gh; g_wi_lo[rg] = __float2bfloat16(vg - __bfloat162float(gh));
    }
}

// gather + split activations
__global__ void pack_x1_kernel(const float* __restrict__ nh, const float* __restrict__ nc,
                               const float* __restrict__ lab, const float* __restrict__ le) {
    int p  = blockIdx.x;
    int br = blockIdx.y;
    if (p >= g_cnt[br]) return;
    int src = g_idx[br][p];
    bf16* xh = g_x1_hi[br];
    bf16* xl = g_x1_lo[br];
    for (int c = threadIdx.x; c < 1536; c += 256) {
        float v = (c < 512) ? nh[(size_t)src * 512 + c]
                : (c < 1024) ? nc[(size_t)src * 512 + (c - 512)]
                             : lab[(size_t)src * 512 + (c - 1024)];
        bf16 hi = __float2bfloat16(v);
        xh[(size_t)p * 1536 + c] = hi;
        xl[(size_t)p * 1536 + c] = __float2bfloat16(v - __bfloat162float(hi));
    }
    if (br == 1) {
        for (int c = threadIdx.x; c < 512; c += 256) {
            float v = le[(size_t)src * 512 + c];
            bf16 hi = __float2bfloat16(v);
            g_le_hi[(size_t)p * 512 + c] = hi;
            g_le_lo[(size_t)p * 512 + c] = __float2bfloat16(v - __bfloat162float(hi));
        }
    }
}

// ---- stage loader ----
__device__ __forceinline__ void load_stage(uint32_t stu, int job, int br, int m0,
                                           int bx, int k0, int K, int wioff, int tid) {
    const bf16 *ahi, *alo;
    int astr, acol;
    if (job <= 1)      { ahi = g_x1_hi[br]; alo = g_x1_lo[br]; astr = 1536; acol = k0; }
    else if (job == 2) { ahi = g_h1_hi[0];  alo = g_h1_lo[0];  astr = 512;  acol = k0; }
    else {
        if (k0 < 512)  { ahi = g_h1_hi[1];  alo = g_h1_lo[1];  astr = 512;  acol = k0; }
        else           { ahi = g_le_hi;     alo = g_le_lo;     astr = 512;  acol = k0 - 512; }
    }
#pragma unroll
    for (int i = 0; i < 2; ++i) {
        int idx = tid + i * NTH;           // 0..511
        int row = idx >> 2;                // 0..127
        int q   = idx & 3;                 // 16B chunk
        uint32_t d = stu + row * ROWB + q * 16;
        CP_ASYNC16(d,               ahi + (size_t)(m0 + row) * astr + acol + q * 8);
        CP_ASYNC16(d + PLANE_B,     alo + (size_t)(m0 + row) * astr + acol + q * 8);
        int grow = bx * 128 + row;
        CP_ASYNC16(d + 2 * PLANE_B, g_wi_hi + wioff + (size_t)grow * K + k0 + q * 8);
        CP_ASYNC16(d + 3 * PLANE_B, g_wi_lo + wioff + (size_t)grow * K + k0 + q * 8);
    }
    CP_COMMIT();
}

// ---- fused gated GEMM via mma.sync bf16x3 ----
__global__ void __launch_bounds__(NTH, 1)
gate_gemm_mma(int base_job,
              const float* __restrict__ bh_a, const float* __restrict__ bg_a,
              const float* __restrict__ bh_b, const float* __restrict__ bg_b,
              float* __restrict__ out) {
    extern __shared__ char smem[];
    int job = base_job + (int)blockIdx.z;
    int br  = (job == 1 || job == 3) ? 1 : 0;
    int mcnt = g_cnt[br];
    int m0 = blockIdx.y * CTA_M;
    if (m0 >= mcnt) return;
    int bx = blockIdx.x;
    int K  = c_jobK[job];
    int wioff = c_wioff[job];
    int tid = threadIdx.x;
    uint32_t sb = smem_u32(smem);

    float acc[2][8][4];
#pragma unroll
    for (int i = 0; i < 2; ++i)
#pragma unroll
        for (int j = 0; j < 8; ++j)
#pragma unroll
            for (int q = 0; q < 4; ++q) acc[i][j][q] = 0.f;

    const int nchunks = K / BK;
    load_stage(sb, job, br, m0, bx, 0, K, wioff, tid);

    int wid = tid >> 5, lane = tid & 31;
    int wm = (wid & 3) * 32;
    int wn = (wid >> 2) * 64;                       // B-tile row offset
    uint32_t a_off  = (uint32_t)(wm + (lane & 15)) * ROWB + ((lane >> 4) << 4);
    uint32_t b_rowl = (lane & 7);
    uint32_t b_pair = (lane >> 4);                  // 0/1 -> tn offset in x4 pair load
    uint32_t b_kh   = ((lane >> 3) & 1) * 16;

    for (int c = 0; c < nchunks; ++c) {
        int stg = c & 1;
        __syncthreads();                             // stage (c+1)&1 fully consumed
        if (c + 1 < nchunks) {
            load_stage(sb + (stg ^ 1) * STAGE_B, job, br, m0, bx, (c + 1) * BK, K, wioff, tid);
            CP_WAIT1();
        } else {
            CP_WAIT0();
        }
        __syncthreads();                             // stage c visible everywhere
        uint32_t stu = sb + stg * STAGE_B;

#pragma unroll
        for (int s = 0; s < 2; ++s) {
            uint32_t ah[2][4], al[2][4];
#pragma unroll
            for (int tm = 0; tm < 2; ++tm) {
                uint32_t addr = stu + a_off + tm * 16 * ROWB + s * 32;
                LDSM_X4(ah[tm], addr);
                LDSM_X4(al[tm], addr + PLANE_B);
            }
            uint32_t bhf[8][2], blf[8][2];
#pragma unroll
            for (int tn = 0; tn < 8; tn += 2) {
                uint32_t row = wn + (tn + b_pair) * 8 + b_rowl;
                uint32_t addr = stu + 2 * PLANE_B + row * ROWB + s * 32 + b_kh;
                uint32_t r[4];
                LDSM_X4(r, addr);
                bhf[tn][0] = r[0]; bhf[tn][1] = r[1];
                bhf[tn + 1][0] = r[2]; bhf[tn + 1][1] = r[3];
                LDSM_X4(r, addr + PLANE_B);
                blf[tn][0] = r[0]; blf[tn][1] = r[1];
                blf[tn + 1][0] = r[2]; blf[tn + 1][1] = r[3];
            }
#pragma unroll
            for (int tm = 0; tm < 2; ++tm)
#pragma unroll
                for (int tn = 0; tn < 8; ++tn) MMA_BF16(acc[tm][tn], ah[tm], bhf[tn]);
#pragma unroll
            for (int tm = 0; tm < 2; ++tm)
#pragma unroll
                for (int tn = 0; tn < 8; ++tn) MMA_BF16(acc[tm][tn], al[tm], bhf[tn]);
#pragma unroll
            for (int tm = 0; tm < 2; ++tm)
#pragma unroll
                for (int tn = 0; tn < 8; ++tn) MMA_BF16(acc[tm][tn], ah[tm], blf[tn]);
        }
    }

    // ---- epilogue: (c0,c1) = (h,g) for one logical n; register-local gate ----
    const float* bh_p = (blockIdx.z == 0) ? bh_a : bh_b;
    const float* bg_p = (blockIdx.z == 0) ? bg_a : bg_b;
    int n_base = bx * 64 + (wid >> 2) * 32 + (lane & 3);
    int m_base = m0 + wm + (lane >> 2);
    bf16* h1h = g_h1_hi[br];
    bf16* h1l = g_h1_lo[br];

#pragma unroll
    for (int tn = 0; tn < 8; ++tn) {
        int n = n_base + tn * 4;
        float bhv = __ldg(bh_p + n);
        float bgv = __ldg(bg_p + n);
#pragma unroll
        for (int tm = 0; tm < 2; ++tm)
#pragma unroll
            for (int rr = 0; rr < 2; ++rr) {
                int m = m_base + tm * 16 + rr * 8;
                if (m < mcnt) {
                    float x = acc[tm][tn][rr * 2 + 0] + bhv;
                    float y = acc[tm][tn][rr * 2 + 1] + bgv;
                    float r = tanhf(x) * (1.0f / (1.0f + __expf(-y)));
                    if (job < 2) {
                        bf16 hi = __float2bfloat16(r);
                        h1h[(size_t)m * 512 + n] = hi;
                        h1l[(size_t)m * 512 + n] = __float2bfloat16(r - __bfloat162float(hi));
                    } else {
                        out[(size_t)g_idx[br][m] * 512 + n] = r;
                    }
                }
            }
    }
}

// ---- launch ----
extern "C" void kernel_launch(void* const* d_in, const int* in_sizes, int n_in,
                              void* d_out, int out_size) {
    const float* node_hidden     = (const float*)d_in[0];
    const float* node_context    = (const float*)d_in[1];
    const float* label_embedding = (const float*)d_in[2];
    const float* left_embedding  = (const float*)d_in[3];
    const int*   group           = (const int*)  d_in[4];
    const float* Wl1h = (const float*)d_in[5];
    const float* bl1h = (const float*)d_in[6];
    const float* Wl1g = (const float*)d_in[7];
    const float* bl1g = (const float*)d_in[8];
    const float* Wl2h = (const float*)d_in[9];
    const float* bl2h = (const float*)d_in[10];
    const float* Wl2g = (const float*)d_in[11];
    const float* bl2g = (const float*)d_in[12];
    const float* Wr1h = (const float*)d_in[13];
    const float* br1h = (const float*)d_in[14];
    const float* Wr1g = (const float*)d_in[15];
    const float* br1g = (const float*)d_in[16];
    const float* Wr2h = (const float*)d_in[17];
    const float* br2h = (const float*)d_in[18];
    const float* Wr2g = (const float*)d_in[19];
    const float* br2g = (const float*)d_in[20];
    (void)in_sizes; (void)n_in;

    float* out_children = (float*)d_out;
    float* out_mask     = (float*)d_out + (size_t)B_ * H_;
    int write_mask = (out_size >= (int)((size_t)B_ * H_ + B_)) ? 1 : 0;

    cudaFuncSetAttribute(gate_gemm_mma, cudaFuncAttributeMaxDynamicSharedMemorySize, SMEM_DYN);

    zero_cnt_kernel<<<1, 32>>>();
    build_idx_kernel<<<B_ / 256, 256>>>(group, out_mask, write_mask);
    prepack_wi_kernel<<<dim3(48, 16, 4), dim3(32, 8)>>>(Wl1h, Wl1g, Wr1h, Wr1g,
                                                        Wl2h, Wl2g, Wr2h, Wr2g);
    pack_x1_kernel<<<dim3(B_, 2), 256>>>(node_hidden, node_context,
                                         label_embedding, left_embedding);
    zero_out_kernel<<<(B_ * (H_ / 4) + 255) / 256, 256>>>(out_children);

    dim3 grid(H_ / 64, B_ / CTA_M, 2);   // 8 x 256 x 2; idle M-blocks exit early
    // layer 1: jobs 0 (left) and 1 (right)
    gate_gemm_mma<<<grid, NTH, SMEM_DYN>>>(0, bl1h, bl1g, br1h, br1g, nullptr);
    // layer 2: jobs 2 (left) and 3 (right), scatter straight into d_out
    gate_gemm_mma<<<grid, NTH, SMEM_DYN>>>(2, bl2h, bl2g, br2h, br2g, out_children);
}